// round 2
// baseline (speedup 1.0000x reference)
#include <cuda_runtime.h>
#include <cuda_bf16.h>
#include <stdint.h>

// ---------------- problem constants (fixed shapes) ----------------
#define BATCH 256
#define TT    250
#define CC    700
#define KP    704          // C padded to multiple of 32
#define H1    1024
#define H2    512
#define OO    20
#define BT    (BATCH*TT)   // 64000

// ---------------- device scratch ----------------
static __device__ __nv_bfloat16 g_xd[(size_t)BT * KP];    // delayed input bf16, [r][k] ~90MB
static __device__ __nv_bfloat16 g_WinB[H1 * KP];          // W_in bf16, [h][k] (natural layout, zero-padded k)
static __device__ float g_Iin[(size_t)BT * H1];           // [r][h] fp32, ~262MB
static __device__ float g_Wr1T[H1 * H1];                  // [j][h]
static __device__ float g_W2T[H1 * H2];                   // [j1][h2]
static __device__ float g_Wr2T[H2 * H2];                  // [j2][h2]
static __device__ float g_WoT[H2 * OO];                   // [j2][o]

// ---------------- K1: weight prep (bf16 convert + fp32 transposes) ----------------
__global__ void k_prep(const float* __restrict__ Win, const float* __restrict__ Wr1,
                       const float* __restrict__ W2, const float* __restrict__ Wr2,
                       const float* __restrict__ Wo)
{
    const int N0 = H1 * KP;          // WinB (bf16, padded)
    const int N1 = H1 * H1;          // Wr1T
    const int N2 = H1 * H2;          // W2T
    const int N3 = H2 * H2;          // Wr2T
    const int N4 = H2 * OO;          // WoT
    const int total = N0 + N1 + N2 + N3 + N4;
    for (int i = blockIdx.x * blockDim.x + threadIdx.x; i < total; i += gridDim.x * blockDim.x) {
        int r = i;
        if (r < N0) {
            int h = r / KP, k = r % KP;
            g_WinB[r] = __float2bfloat16((k < CC) ? Win[h * CC + k] : 0.0f);
            continue;
        }
        r -= N0;
        if (r < N1) { int j = r / H1, h = r % H1; g_Wr1T[r] = Wr1[h * H1 + j]; continue; }
        r -= N1;
        if (r < N2) { int j = r / H2, h = r % H2; g_W2T[r] = W2[h * H1 + j]; continue; }
        r -= N2;
        if (r < N3) { int j = r / H2, h = r % H2; g_Wr2T[r] = Wr2[h * H2 + j]; continue; }
        r -= N3;
        { int j = r / OO, o = r % OO; g_WoT[r] = Wo[o * H2 + j]; }
    }
}

// ---------------- K2: build delayed input (bf16, row-major padded) ----------------
// grid: (8 t-tiles, 256 batches), block (32,32). Staging transpose so both the
// x reads and the g_xd writes are coalesced.
__global__ void k_build_xd(const float* __restrict__ x, const int* __restrict__ delays)
{
    __shared__ float stage[92][32];
    __shared__ int dsh[KP];
    const int b  = blockIdx.y;
    const int t0 = blockIdx.x * 32;
    const int tx = threadIdx.x, ty = threadIdx.y;
    const int tid = ty * 32 + tx;
    for (int i = tid; i < KP; i += 1024) dsh[i] = (i < CC) ? delays[i] : 0;
    __syncthreads();

    for (int c0 = 0; c0 < KP; c0 += 32) {
        for (int r = ty; r < 92; r += 32) {
            int tg = t0 - 60 + r;
            int c  = c0 + tx;
            float v = 0.0f;
            if (tg >= 0 && tg < TT && c < CC) v = x[((size_t)b * TT + tg) * CC + c];
            stage[r][tx] = v;
        }
        __syncthreads();
        int t = t0 + ty;
        int c = c0 + tx;
        if (t < TT) {
            float v = 0.0f;
            if (c < CC) {
                int row = ty + 60 - dsh[c];     // (t - d) - (t0 - 60), in [0,91]
                v = stage[row][tx];
            }
            g_xd[((size_t)b * TT + t) * KP + c] = __float2bfloat16(v);
        }
        __syncthreads();
    }
}

// ---------------- K3: bf16 tensor-core GEMM  I_in = xd @ W_in^T ----------------
// C[r][h] = sum_k A[r][k] * B[h][k];  mma.m16n8k16.row.col, fp32 accum.
// Block tile 128x128x32, 8 warps (2 along M x 4 along N), warp tile 64x32.
#define BM 128
#define BN 128
#define BKK 32
#define SMSTR 40   // padded bf16 row stride (80B: 16B-aligned, conflict-free rows)

__global__ void __launch_bounds__(256) k_gemm()
{
    __shared__ __nv_bfloat16 As[2][BM * SMSTR];
    __shared__ __nv_bfloat16 Bs[2][BN * SMSTR];

    const int tid    = threadIdx.x;
    const int warpId = tid >> 5;
    const int lane   = tid & 31;
    const int g      = lane >> 2;        // group row
    const int t4     = lane & 3;         // thread-in-group

    const int row0 = blockIdx.y * BM;
    const int col0 = blockIdx.x * BN;
    const int wm   = (warpId & 1) * 64;  // warp M offset in tile
    const int wn   = (warpId >> 1) * 32; // warp N offset in tile

    // global load assignment: 2 x 16B per thread per tile (A and B identical pattern)
    // tile = 128 rows x 32 cols bf16 = 512 x 8-elem segments
    const int lrow0 = tid >> 2;                // 0..63   (two rows: lrow0, lrow0+64)
    const int lseg  = (tid & 3) * 8;           // 0,8,16,24

    float acc[4][4][4];
#pragma unroll
    for (int i = 0; i < 4; ++i)
#pragma unroll
        for (int j = 0; j < 4; ++j)
#pragma unroll
            for (int c = 0; c < 4; ++c) acc[i][j][c] = 0.0f;

    const __nv_bfloat16* Ag = g_xd   + (size_t)row0 * KP;
    const __nv_bfloat16* Bg = g_WinB + (size_t)col0 * KP;

    // preload tile 0
    {
        uint4 a0 = *(const uint4*)(Ag + (size_t)lrow0 * KP + lseg);
        uint4 a1 = *(const uint4*)(Ag + (size_t)(lrow0 + 64) * KP + lseg);
        uint4 b0 = *(const uint4*)(Bg + (size_t)lrow0 * KP + lseg);
        uint4 b1 = *(const uint4*)(Bg + (size_t)(lrow0 + 64) * KP + lseg);
        *(uint4*)&As[0][lrow0 * SMSTR + lseg]        = a0;
        *(uint4*)&As[0][(lrow0 + 64) * SMSTR + lseg] = a1;
        *(uint4*)&Bs[0][lrow0 * SMSTR + lseg]        = b0;
        *(uint4*)&Bs[0][(lrow0 + 64) * SMSTR + lseg] = b1;
    }
    __syncthreads();

    const int NK = KP / BKK;   // 22
    int buf = 0;
    for (int kt = 0; kt < NK; ++kt) {
        // prefetch next tile into registers
        uint4 a0, a1, b0, b1;
        if (kt + 1 < NK) {
            const int k0 = (kt + 1) * BKK;
            a0 = *(const uint4*)(Ag + (size_t)lrow0 * KP + k0 + lseg);
            a1 = *(const uint4*)(Ag + (size_t)(lrow0 + 64) * KP + k0 + lseg);
            b0 = *(const uint4*)(Bg + (size_t)lrow0 * KP + k0 + lseg);
            b1 = *(const uint4*)(Bg + (size_t)(lrow0 + 64) * KP + k0 + lseg);
        }

        // compute on current buffer
        const __nv_bfloat16* Asb = As[buf];
        const __nv_bfloat16* Bsb = Bs[buf];
#pragma unroll
        for (int ks = 0; ks < BKK; ks += 16) {
            uint32_t af[4][4];   // [mtile][4 regs]
            uint32_t bf[4][2];   // [ntile][2 regs]
#pragma unroll
            for (int i = 0; i < 4; ++i) {
                const int mb = wm + i * 16;
                af[i][0] = *(const uint32_t*)&Asb[(mb + g)     * SMSTR + ks + 2 * t4];
                af[i][1] = *(const uint32_t*)&Asb[(mb + g + 8) * SMSTR + ks + 2 * t4];
                af[i][2] = *(const uint32_t*)&Asb[(mb + g)     * SMSTR + ks + 2 * t4 + 8];
                af[i][3] = *(const uint32_t*)&Asb[(mb + g + 8) * SMSTR + ks + 2 * t4 + 8];
            }
#pragma unroll
            for (int j = 0; j < 4; ++j) {
                const int nb = wn + j * 8;
                bf[j][0] = *(const uint32_t*)&Bsb[(nb + g) * SMSTR + ks + 2 * t4];
                bf[j][1] = *(const uint32_t*)&Bsb[(nb + g) * SMSTR + ks + 2 * t4 + 8];
            }
#pragma unroll
            for (int i = 0; i < 4; ++i)
#pragma unroll
                for (int j = 0; j < 4; ++j) {
                    asm volatile(
                        "mma.sync.aligned.m16n8k16.row.col.f32.bf16.bf16.f32 "
                        "{%0,%1,%2,%3}, {%4,%5,%6,%7}, {%8,%9}, {%0,%1,%2,%3};\n"
                        : "+f"(acc[i][j][0]), "+f"(acc[i][j][1]),
                          "+f"(acc[i][j][2]), "+f"(acc[i][j][3])
                        : "r"(af[i][0]), "r"(af[i][1]), "r"(af[i][2]), "r"(af[i][3]),
                          "r"(bf[j][0]), "r"(bf[j][1]));
                }
        }
        __syncthreads();

        // store prefetched tile
        if (kt + 1 < NK) {
            const int nb = buf ^ 1;
            *(uint4*)&As[nb][lrow0 * SMSTR + lseg]        = a0;
            *(uint4*)&As[nb][(lrow0 + 64) * SMSTR + lseg] = a1;
            *(uint4*)&Bs[nb][lrow0 * SMSTR + lseg]        = b0;
            *(uint4*)&Bs[nb][(lrow0 + 64) * SMSTR + lseg] = b1;
            __syncthreads();
            buf = nb;
        }
    }

    // epilogue: each lane owns rows (g, g+8), cols (2t, 2t+1) per 16x8 tile
#pragma unroll
    for (int i = 0; i < 4; ++i) {
#pragma unroll
        for (int j = 0; j < 4; ++j) {
            const int r0 = row0 + wm + i * 16 + g;
            const int c  = col0 + wn + j * 8 + 2 * t4;
            *(float2*)&g_Iin[(size_t)r0 * H1 + c]       = make_float2(acc[i][j][0], acc[i][j][1]);
            *(float2*)&g_Iin[(size_t)(r0 + 8) * H1 + c] = make_float2(acc[i][j][2], acc[i][j][3]);
        }
    }
}

// ---------------- K4: per-batch recurrent scan ----------------
__global__ void __launch_bounds__(1024, 2) k_scan(
    const float* __restrict__ alpha1, const float* __restrict__ rho1, const float* __restrict__ beta_a1,
    const float* __restrict__ alpha2, const float* __restrict__ rho2, const float* __restrict__ beta_a2,
    const float* __restrict__ beta_out, float* __restrict__ out)
{
    __shared__ int cnt1[2], cnt2[2];
    __shared__ int act1[2][H1];
    __shared__ int act2[2][H2];

    const int b = blockIdx.x;
    const int h = threadIdx.x;

    const float al1 = alpha1[h];
    const float om1 = 1.0f - al1;
    const float r1  = rho1[h];
    const float ba1 = beta_a1[h];
    float v1 = 0.0f, ad1 = 0.0f, s1 = 0.0f;

    float al2 = 0.f, om2 = 0.f, r2 = 0.f, ba2 = 0.f;
    float v2 = 0.0f, ad2 = 0.0f, s2 = 0.0f;
    if (h < H2) { al2 = alpha2[h]; om2 = 1.0f - al2; r2 = rho2[h]; ba2 = beta_a2[h]; }

    float bo = 0.f, obo = 0.f, vo = 0.0f, vos = 0.0f;
    if (h < OO) { bo = beta_out[h]; obo = 1.0f - bo; }

    if (h == 0) { cnt1[0] = cnt1[1] = 0; cnt2[0] = cnt2[1] = 0; }
    __syncthreads();

    const float* Ib = g_Iin + (size_t)b * TT * H1 + h;
    float Inext = Ib[0];
    int p = 0;

    for (int t = 0; t < TT; ++t) {
        const int q = p ^ 1;
        float I1 = Inext;
        if (t < TT - 1) Inext = Ib[(size_t)(t + 1) * H1];   // prefetch next step

        if (h == 0) { cnt1[q] = 0; cnt2[q] = 0; }

        // layer 1: recurrent gather over previous step's active list
        const int n1 = cnt1[p];
        for (int i = 0; i < n1; ++i) I1 += g_Wr1T[act1[p][i] * H1 + h];
        v1 = al1 * v1 + om1 * I1 - s1 - ad1;                // soft reset (THRESH=1)
        const float ns1 = (v1 >= 1.0f) ? 1.0f : 0.0f;
        ad1 = r1 * ad1 + ba1 * ns1;
        s1 = ns1;
        __syncthreads();

        if (ns1 != 0.0f) { int idx = atomicAdd(&cnt1[q], 1); act1[q][idx] = h; }
        __syncthreads();

        // layer 2
        if (h < H2) {
            float I2 = 0.0f;
            const int m1 = cnt1[q];
            for (int i = 0; i < m1; ++i) I2 += g_W2T[act1[q][i] * H2 + h];
            const int n2 = cnt2[p];
            for (int i = 0; i < n2; ++i) I2 += g_Wr2T[act2[p][i] * H2 + h];
            v2 = al2 * v2 + om2 * I2 - s2 - ad2;
            const float ns2 = (v2 >= 1.0f) ? 1.0f : 0.0f;
            ad2 = r2 * ad2 + ba2 * ns2;
            s2 = ns2;
            if (ns2 != 0.0f) { int idx = atomicAdd(&cnt2[q], 1); act2[q][idx] = h; }
        }
        __syncthreads();

        // readout
        if (h < OO) {
            float Io = 0.0f;
            const int m2 = cnt2[q];
            for (int i = 0; i < m2; ++i) Io += g_WoT[act2[q][i] * OO + h];
            vo = bo * vo + obo * Io;
            vos += vo;
        }
        p = q;
    }

    if (h < OO) out[b * OO + h] = vos * (1.0f / (float)TT);
}

// ---------------- launch ----------------
extern "C" void kernel_launch(void* const* d_in, const int* in_sizes, int n_in,
                              void* d_out, int out_size)
{
    const float* x       = (const float*)d_in[0];
    const int*   delays  = (const int*)  d_in[1];
    const float* W_in    = (const float*)d_in[2];
    const float* W_rec1  = (const float*)d_in[3];
    const float* W2      = (const float*)d_in[4];
    const float* W_rec2  = (const float*)d_in[5];
    const float* W_out   = (const float*)d_in[6];
    const float* alpha1  = (const float*)d_in[7];
    const float* rho1    = (const float*)d_in[8];
    const float* beta_a1 = (const float*)d_in[9];
    const float* alpha2  = (const float*)d_in[10];
    const float* rho2    = (const float*)d_in[11];
    const float* beta_a2 = (const float*)d_in[12];
    const float* beta_out= (const float*)d_in[13];
    float* out = (float*)d_out;

    k_prep<<<2560, 1024>>>(W_in, W_rec1, W2, W_rec2, W_out);

    {
        dim3 grid(8, BATCH);
        dim3 block(32, 32);
        k_build_xd<<<grid, block>>>(x, delays);
    }

    {
        dim3 grid(H1 / BN, BT / BM);   // (8, 500)
        k_gemm<<<grid, 256>>>();
    }

    k_scan<<<BATCH, 1024>>>(alpha1, rho1, beta_a1, alpha2, rho2, beta_a2, beta_out, out);
}

// round 4
// speedup vs baseline: 1.7185x; 1.7185x over previous
#include <cuda_runtime.h>
#include <cuda_bf16.h>
#include <stdint.h>

// ---------------- problem constants (fixed shapes) ----------------
#define BATCH 256
#define TT    250
#define CC    700
#define KP    704          // C padded to multiple of 32
#define H1    1024
#define H2    512
#define OO    20
#define BT    (BATCH*TT)   // 64000

// ---------------- device scratch ----------------
static __device__ __nv_bfloat16 g_xd[(size_t)BT * KP];    // delayed input bf16 [r][k], 90MB
static __device__ __nv_bfloat16 g_WinB[H1 * KP];          // W_in bf16 [h][k], zero-padded k
static __device__ __nv_bfloat16 g_IinB[(size_t)BT * H1];  // I_in bf16 [r][h], 131MB
static __device__ float g_Wr1T[H1 * H1];                  // [j][h]
static __device__ float g_W2T[H1 * H2];                   // [j1][h2]
static __device__ float g_Wr2T[H2 * H2];                  // [j2][h2]
static __device__ float g_WoT[H2 * OO];                   // [j2][o]

// ---------------- K1: weight prep ----------------
__global__ void k_prep(const float* __restrict__ Win, const float* __restrict__ Wr1,
                       const float* __restrict__ W2, const float* __restrict__ Wr2,
                       const float* __restrict__ Wo)
{
    const int N0 = H1 * KP;
    const int N1 = H1 * H1;
    const int N2 = H1 * H2;
    const int N3 = H2 * H2;
    const int N4 = H2 * OO;
    const int total = N0 + N1 + N2 + N3 + N4;
    for (int i = blockIdx.x * blockDim.x + threadIdx.x; i < total; i += gridDim.x * blockDim.x) {
        int r = i;
        if (r < N0) {
            int h = r / KP, k = r % KP;
            g_WinB[r] = __float2bfloat16((k < CC) ? Win[h * CC + k] : 0.0f);
            continue;
        }
        r -= N0;
        if (r < N1) { int j = r / H1, h = r % H1; g_Wr1T[r] = Wr1[h * H1 + j]; continue; }
        r -= N1;
        if (r < N2) { int j = r / H2, h = r % H2; g_W2T[r] = W2[h * H1 + j]; continue; }
        r -= N2;
        if (r < N3) { int j = r / H2, h = r % H2; g_Wr2T[r] = Wr2[h * H2 + j]; continue; }
        r -= N3;
        { int j = r / OO, o = r % OO; g_WoT[r] = Wo[o * H2 + j]; }
    }
}

// ---------------- K2: build delayed input (125-step t-tiles) ----------------
__global__ void k_build_xd(const float* __restrict__ x, const int* __restrict__ delays)
{
    __shared__ float stage[185][32];
    __shared__ int dsh[KP];
    const int b  = blockIdx.y;
    const int t0 = blockIdx.x * 125;
    const int tx = threadIdx.x, ty = threadIdx.y;
    const int tid = ty * 32 + tx;
    for (int i = tid; i < KP; i += 1024) dsh[i] = (i < CC) ? delays[i] : 0;

    for (int c0 = 0; c0 < KP; c0 += 32) {
        __syncthreads();
        for (int idx = tid; idx < 185 * 32; idx += 1024) {
            int r = idx >> 5;
            int c = c0 + (idx & 31);
            int tg = t0 - 60 + r;
            float v = 0.0f;
            if (tg >= 0 && tg < TT && c < CC) v = x[((size_t)b * TT + tg) * CC + c];
            stage[r][idx & 31] = v;
        }
        __syncthreads();
        const int c = c0 + tx;
        const int d = dsh[c];
        for (int tt = ty; tt < 125; tt += 32) {
            float v = (c < CC) ? stage[tt + 60 - d][tx] : 0.0f;
            g_xd[((size_t)b * TT + t0 + tt) * KP + c] = __float2bfloat16(v);
        }
    }
}

// ---------------- K3: bf16 HMMA GEMM with cp.async + ldmatrix ----------------
// Block 128x128x32, 3-stage cp.async pipeline (dynamic smem), 8 warps (2M x 4N).
#define BM 128
#define BN 128
#define BKK 32
#define SMSTR 40   // bf16 row stride (80B): 16B aligned, ldmatrix conflict-free
#define GEMM_SMEM (3 * (BM + BN) * SMSTR * 2)   // 61440 bytes

#define CP_ASYNC16(dst_u32, src_ptr) \
    asm volatile("cp.async.cg.shared.global [%0], [%1], 16;\n" :: "r"(dst_u32), "l"(src_ptr))
#define CP_COMMIT() asm volatile("cp.async.commit_group;\n" ::)
#define CP_WAIT1()  asm volatile("cp.async.wait_group 1;\n" ::)

__global__ void __launch_bounds__(256) k_gemm()
{
    extern __shared__ __nv_bfloat16 smem[];
    __nv_bfloat16* Abase = smem;                       // 3 stages of BM*SMSTR
    __nv_bfloat16* Bbase = smem + 3 * BM * SMSTR;      // 3 stages of BN*SMSTR

    const int tid    = threadIdx.x;
    const int warpId = tid >> 5;
    const int lane   = tid & 31;
    const int g      = lane >> 2;
    const int t4     = lane & 3;

    const int row0 = blockIdx.y * BM;
    const int col0 = blockIdx.x * BN;
    const int wm   = (warpId & 1) * 64;
    const int wn   = (warpId >> 1) * 32;

    const int lrow0 = tid >> 2;            // 0..63
    const int lseg  = (tid & 3) * 8;       // bf16 elems: 0,8,16,24

    const __nv_bfloat16* Ag = g_xd   + (size_t)row0 * KP;
    const __nv_bfloat16* Bg = g_WinB + (size_t)col0 * KP;

    uint32_t sA[3], sB[3];
#pragma unroll
    for (int s = 0; s < 3; ++s) {
        sA[s] = (uint32_t)__cvta_generic_to_shared(Abase + s * BM * SMSTR);
        sB[s] = (uint32_t)__cvta_generic_to_shared(Bbase + s * BN * SMSTR);
    }

    const int aoff = ((wm + (lane & 15)) * SMSTR + (lane >> 4) * 8) * 2;
    const int boff = ((wn + (lane & 7) + ((lane >> 4) << 3)) * SMSTR + ((lane >> 3) & 1) * 8) * 2;

    float acc[4][4][4];
#pragma unroll
    for (int i = 0; i < 4; ++i)
#pragma unroll
        for (int j = 0; j < 4; ++j)
#pragma unroll
            for (int c = 0; c < 4; ++c) acc[i][j][c] = 0.0f;

    const int NK = KP / BKK;   // 22

#pragma unroll
    for (int s = 0; s < 2; ++s) {
        const int k0 = s * BKK;
        CP_ASYNC16(sA[s] + (lrow0 * SMSTR + lseg) * 2,        Ag + (size_t)lrow0 * KP + k0 + lseg);
        CP_ASYNC16(sA[s] + ((lrow0 + 64) * SMSTR + lseg) * 2, Ag + (size_t)(lrow0 + 64) * KP + k0 + lseg);
        CP_ASYNC16(sB[s] + (lrow0 * SMSTR + lseg) * 2,        Bg + (size_t)lrow0 * KP + k0 + lseg);
        CP_ASYNC16(sB[s] + ((lrow0 + 64) * SMSTR + lseg) * 2, Bg + (size_t)(lrow0 + 64) * KP + k0 + lseg);
        CP_COMMIT();
    }

    int st = 0;
    for (int kt = 0; kt < NK; ++kt) {
        CP_WAIT1();
        __syncthreads();

        if (kt + 2 < NK) {
            const int s = (st + 2 >= 3) ? st - 1 : st + 2;   // (kt+2)%3
            const int k0 = (kt + 2) * BKK;
            CP_ASYNC16(sA[s] + (lrow0 * SMSTR + lseg) * 2,        Ag + (size_t)lrow0 * KP + k0 + lseg);
            CP_ASYNC16(sA[s] + ((lrow0 + 64) * SMSTR + lseg) * 2, Ag + (size_t)(lrow0 + 64) * KP + k0 + lseg);
            CP_ASYNC16(sB[s] + (lrow0 * SMSTR + lseg) * 2,        Bg + (size_t)lrow0 * KP + k0 + lseg);
            CP_ASYNC16(sB[s] + ((lrow0 + 64) * SMSTR + lseg) * 2, Bg + (size_t)(lrow0 + 64) * KP + k0 + lseg);
        }
        CP_COMMIT();

        const uint32_t aBase = sA[st] + aoff;
        const uint32_t bBase = sB[st] + boff;
#pragma unroll
        for (int ks = 0; ks < BKK; ks += 16) {
            uint32_t af[4][4];
            uint32_t bq[2][4];
#pragma unroll
            for (int i = 0; i < 4; ++i) {
                asm volatile("ldmatrix.sync.aligned.m8n8.x4.shared.b16 {%0,%1,%2,%3}, [%4];"
                             : "=r"(af[i][0]), "=r"(af[i][1]), "=r"(af[i][2]), "=r"(af[i][3])
                             : "r"(aBase + (i * 16 * SMSTR + ks) * 2));
            }
#pragma unroll
            for (int j2 = 0; j2 < 2; ++j2) {
                asm volatile("ldmatrix.sync.aligned.m8n8.x4.shared.b16 {%0,%1,%2,%3}, [%4];"
                             : "=r"(bq[j2][0]), "=r"(bq[j2][1]), "=r"(bq[j2][2]), "=r"(bq[j2][3])
                             : "r"(bBase + (j2 * 16 * SMSTR + ks) * 2));
            }
#pragma unroll
            for (int i = 0; i < 4; ++i)
#pragma unroll
                for (int j = 0; j < 4; ++j) {
                    const uint32_t b0 = bq[j >> 1][(j & 1) * 2];
                    const uint32_t b1 = bq[j >> 1][(j & 1) * 2 + 1];
                    asm volatile(
                        "mma.sync.aligned.m16n8k16.row.col.f32.bf16.bf16.f32 "
                        "{%0,%1,%2,%3}, {%4,%5,%6,%7}, {%8,%9}, {%0,%1,%2,%3};\n"
                        : "+f"(acc[i][j][0]), "+f"(acc[i][j][1]),
                          "+f"(acc[i][j][2]), "+f"(acc[i][j][3])
                        : "r"(af[i][0]), "r"(af[i][1]), "r"(af[i][2]), "r"(af[i][3]),
                          "r"(b0), "r"(b1));
                }
        }
        st = (st + 1 == 3) ? 0 : st + 1;
    }

    // epilogue: bf16 pairs
#pragma unroll
    for (int i = 0; i < 4; ++i) {
#pragma unroll
        for (int j = 0; j < 4; ++j) {
            const int r0 = row0 + wm + i * 16 + g;
            const int c  = col0 + wn + j * 8 + 2 * t4;
            __nv_bfloat162 p0 = __float22bfloat162_rn(make_float2(acc[i][j][0], acc[i][j][1]));
            __nv_bfloat162 p1 = __float22bfloat162_rn(make_float2(acc[i][j][2], acc[i][j][3]));
            *reinterpret_cast<__nv_bfloat162*>(&g_IinB[(size_t)r0 * H1 + c])       = p0;
            *reinterpret_cast<__nv_bfloat162*>(&g_IinB[(size_t)(r0 + 8) * H1 + c]) = p1;
        }
    }
}

// ---------------- K4: per-batch recurrent scan ----------------
__global__ void __launch_bounds__(512, 2) k_scan(
    const float* __restrict__ alpha1, const float* __restrict__ rho1, const float* __restrict__ beta_a1,
    const float* __restrict__ alpha2, const float* __restrict__ rho2, const float* __restrict__ beta_a2,
    const float* __restrict__ beta_out, float* __restrict__ out)
{
    __shared__ int cnt1[2], cnt2[2];
    __shared__ int act1[2][H1];
    __shared__ int act2[2][H2];

    const int b   = blockIdx.x;
    const int tid = threadIdx.x;
    const int h0  = 2 * tid;

    const float2 al1 = *(const float2*)&alpha1[h0];
    const float2 r1  = *(const float2*)&rho1[h0];
    const float2 ba1 = *(const float2*)&beta_a1[h0];
    float v1x = 0.f, v1y = 0.f, a1x = 0.f, a1y = 0.f, s1x = 0.f, s1y = 0.f;

    float2 al2 = make_float2(0.f, 0.f), r2 = al2, ba2 = al2;
    float v2x = 0.f, v2y = 0.f, a2x = 0.f, a2y = 0.f, s2x = 0.f, s2y = 0.f;
    if (tid < H2 / 2) {
        al2 = *(const float2*)&alpha2[h0];
        r2  = *(const float2*)&rho2[h0];
        ba2 = *(const float2*)&beta_a2[h0];
    }

    float bo = 0.f, obo = 0.f, vo = 0.f, vos = 0.f;
    if (tid < OO) { bo = beta_out[tid]; obo = 1.0f - bo; }

    if (tid == 0) { cnt1[0] = cnt1[1] = 0; cnt2[0] = cnt2[1] = 0; }
    __syncthreads();

    const uint32_t* Ib = reinterpret_cast<const uint32_t*>(g_IinB + (size_t)b * TT * H1 + h0);
    uint32_t buf0 = Ib[0 * (H1 / 2)];
    uint32_t buf1 = Ib[1 * (H1 / 2)];
    uint32_t buf2 = Ib[2 * (H1 / 2)];
    uint32_t buf3 = Ib[3 * (H1 / 2)];
    int p = 0;

    auto step = [&](uint32_t packed, uint32_t& slot, int tn) {
        const __nv_bfloat162 bp = *reinterpret_cast<const __nv_bfloat162*>(&packed);
        float I1x = __low2float(bp);
        float I1y = __high2float(bp);
        if (tn < TT) slot = Ib[(size_t)tn * (H1 / 2)];   // prefetch 4 ahead

        const int q = p ^ 1;
        if (tid == 0) { cnt1[q] = 0; cnt2[q] = 0; }

        const int n1 = cnt1[p];
        for (int i = 0; i < n1; ++i) {
            const float2 w = *(const float2*)&g_Wr1T[act1[p][i] * H1 + h0];
            I1x += w.x; I1y += w.y;
        }
        v1x = al1.x * v1x + (1.0f - al1.x) * I1x - s1x - a1x;
        v1y = al1.y * v1y + (1.0f - al1.y) * I1y - s1y - a1y;
        const float ns1x = (v1x >= 1.0f) ? 1.0f : 0.0f;
        const float ns1y = (v1y >= 1.0f) ? 1.0f : 0.0f;
        a1x = r1.x * a1x + ba1.x * ns1x;
        a1y = r1.y * a1y + ba1.y * ns1y;
        s1x = ns1x; s1y = ns1y;
        __syncthreads();                        // resets done; p-lists consumed

        if (ns1x != 0.0f) { int idx = atomicAdd(&cnt1[q], 1); act1[q][idx] = h0; }
        if (ns1y != 0.0f) { int idx = atomicAdd(&cnt1[q], 1); act1[q][idx] = h0 + 1; }
        __syncthreads();                        // act1[q] complete

        if (tid < H2 / 2) {
            float I2x = 0.f, I2y = 0.f;
            const int m1 = cnt1[q];
            for (int i = 0; i < m1; ++i) {
                const float2 w = *(const float2*)&g_W2T[act1[q][i] * H2 + h0];
                I2x += w.x; I2y += w.y;
            }
            const int n2 = cnt2[p];
            for (int i = 0; i < n2; ++i) {
                const float2 w = *(const float2*)&g_Wr2T[act2[p][i] * H2 + h0];
                I2x += w.x; I2y += w.y;
            }
            v2x = al2.x * v2x + (1.0f - al2.x) * I2x - s2x - a2x;
            v2y = al2.y * v2y + (1.0f - al2.y) * I2y - s2y - a2y;
            const float ns2x = (v2x >= 1.0f) ? 1.0f : 0.0f;
            const float ns2y = (v2y >= 1.0f) ? 1.0f : 0.0f;
            a2x = r2.x * a2x + ba2.x * ns2x;
            a2y = r2.y * a2y + ba2.y * ns2y;
            s2x = ns2x; s2y = ns2y;
            if (ns2x != 0.0f) { int idx = atomicAdd(&cnt2[q], 1); act2[q][idx] = h0; }
            if (ns2y != 0.0f) { int idx = atomicAdd(&cnt2[q], 1); act2[q][idx] = h0 + 1; }
        }
        __syncthreads();                        // act2[q] complete

        if (tid < OO) {
            float Io = 0.f;
            const int m2 = cnt2[q];
            for (int i = 0; i < m2; ++i) Io += g_WoT[act2[q][i] * OO + tid];
            vo = bo * vo + obo * Io;
            vos += vo;
        }
        p = q;
    };

    for (int t = 0; t < 248; t += 4) {
        step(buf0, buf0, t + 4);
        step(buf1, buf1, t + 5);
        step(buf2, buf2, t + 6);
        step(buf3, buf3, t + 7);
    }
    step(buf0, buf0, TT);   // t = 248
    step(buf1, buf1, TT);   // t = 249

    if (tid < OO) out[b * OO + tid] = vos * (1.0f / (float)TT);
}

// ---------------- launch ----------------
extern "C" void kernel_launch(void* const* d_in, const int* in_sizes, int n_in,
                              void* d_out, int out_size)
{
    const float* x       = (const float*)d_in[0];
    const int*   delays  = (const int*)  d_in[1];
    const float* W_in    = (const float*)d_in[2];
    const float* W_rec1  = (const float*)d_in[3];
    const float* W2      = (const float*)d_in[4];
    const float* W_rec2  = (const float*)d_in[5];
    const float* W_out   = (const float*)d_in[6];
    const float* alpha1  = (const float*)d_in[7];
    const float* rho1    = (const float*)d_in[8];
    const float* beta_a1 = (const float*)d_in[9];
    const float* alpha2  = (const float*)d_in[10];
    const float* rho2    = (const float*)d_in[11];
    const float* beta_a2 = (const float*)d_in[12];
    const float* beta_out= (const float*)d_in[13];
    float* out = (float*)d_out;

    // allow 60KB dynamic smem for the GEMM (attribute set, not an allocation)
    static int smem_set = 0;
    if (!smem_set) {
        cudaFuncSetAttribute(k_gemm, cudaFuncAttributeMaxDynamicSharedMemorySize, GEMM_SMEM);
        smem_set = 1;
    }

    k_prep<<<2560, 1024>>>(W_in, W_rec1, W2, W_rec2, W_out);

    {
        dim3 grid(2, BATCH);
        dim3 block(32, 32);
        k_build_xd<<<grid, block>>>(x, delays);
    }

    {
        dim3 grid(H1 / BN, BT / BM);   // (8, 500)
        k_gemm<<<grid, 256, GEMM_SMEM>>>();
    }

    k_scan<<<BATCH, 512>>>(alpha1, rho1, beta_a1, alpha2, rho2, beta_a2, beta_out, out);
}